// round 10
// baseline (speedup 1.0000x reference)
#include <cuda_runtime.h>

// ---------------------------------------------------------------------------
// QWTForward: bicubic 2x downsample + 16 scaled copies.
//
//   D = downsample_bicubic(image)                 (4,16,256,256)
//   LL[b, g*16+c]        = D[b,c] * sLL[g]        (4,64,256,256)
//   H [b, g*16+c, band]  = D[b,c] * sH[band][g]   (4,64,3,256,256)
//
// R7: R5 direct structure, row-pair load batching (lower regs, higher occ),
//     late __syncthreads, serial-order filter sums, streaming stores.
// ---------------------------------------------------------------------------

#define B_    4
#define C_    16
#define HIN   512
#define WIN   512
#define HOUT  256
#define WOUT  256
#define PLANE (HOUT * WOUT)                // 65536
#define LL_TOTAL ((size_t)B_ * 64 * PLANE) // 16,777,216 floats

__global__ __launch_bounds__(256)
void qwt_kernel(const float* __restrict__ image,
                const float* __restrict__ gl,
                const float* __restrict__ gh,
                const float* __restrict__ fl,
                const float* __restrict__ fh,
                float* __restrict__ out) {
    __shared__ float sc[16];

    const int tid  = threadIdx.x;
    const int lane = tid & 31;

    // Warp 0: lanes 0-3 each serially sum one 16-tap filter IN INDEX ORDER
    // (sums cancel to ~1e-8; association order is semantically significant).
    if (tid < 32) {
        float s = 0.f;
        if (lane < 4) {
            const float* __restrict__ f =
                (lane == 0) ? gl : (lane == 1) ? gh : (lane == 2) ? fl : fh;
            #pragma unroll
            for (int i = 0; i < 16; i++) s += f[i];
        }
        float vg = __shfl_sync(0xffffffffu, s, 0);
        float vh = __shfl_sync(0xffffffffu, s, 1);
        float vl = __shfl_sync(0xffffffffu, s, 2);
        float vf = __shfl_sync(0xffffffffu, s, 3);
        if (lane < 16) {
            int t = lane;
            bool hiA = (t >= 8);
            bool hiB = (t >> 2) & 1;
            float first  = (t & 1)        ? (hiA ? vf : vl) : (hiA ? vh : vg);
            float second = ((t >> 1) & 1) ? (hiB ? vf : vl) : (hiB ? vh : vg);
            sc[t] = first * second;
        }
    }
    // NOTE: __syncthreads() deferred until just before the store loop.

    // Linear thread id -> (b, c, y, x4); x4 selects 4 consecutive output x.
    unsigned gtid = blockIdx.x * blockDim.x + threadIdx.x;
    int x4 = gtid & 63;          // 64 float4 per row; consecutive within warp
    int y  = (gtid >> 6) & 255;
    int c  = (gtid >> 14) & 15;
    int b  = gtid >> 18;

    const float w0 = -0.09375f, w1 = 0.59375f, w2 = 0.59375f, w3 = -0.09375f;
    const float wv[4] = {w0, w1, w2, w3};

    const float* __restrict__ plane = image + (size_t)(b * C_ + c) * (HIN * WIN);

    int ry[4];
    #pragma unroll
    for (int i = 0; i < 4; i++) {
        int r = 2 * y - 1 + i;
        ry[i] = min(max(r, 0), HIN - 1);
    }

    const int base = 8 * x4;
    const bool left_clamp  = (x4 == 0);
    const bool left_shfl   = (!left_clamp) && (lane > 0);
    const bool right_clamp = (x4 == 63);
    const bool right_shfl  = (!right_clamp) && (lane < 31);
    const bool left_load   = (!left_clamp) && (lane == 0);
    const bool right_load  = (!right_clamp) && (lane == 31);

    float d0 = 0.f, d1 = 0.f, d2 = 0.f, d3 = 0.f;

    // Two row-pairs: 4 vector + up to 4 scalar loads in flight per pair,
    // only ~5 float4 of data live at once (reg pressure down vs full batch).
    #pragma unroll
    for (int pp = 0; pp < 2; pp++) {
        const float* __restrict__ rowA = plane + (size_t)ry[2 * pp]     * WIN;
        const float* __restrict__ rowB = plane + (size_t)ry[2 * pp + 1] * WIN;
        const float4* __restrict__ rowA4 = reinterpret_cast<const float4*>(rowA);
        const float4* __restrict__ rowB4 = reinterpret_cast<const float4*>(rowB);

        float4 bva = __ldg(rowA4 + 2 * x4);
        float4 cva = __ldg(rowA4 + 2 * x4 + 1);
        float4 bvb = __ldg(rowB4 + 2 * x4);
        float4 cvb = __ldg(rowB4 + 2 * x4 + 1);
        float lmA = left_load  ? __ldg(rowA + base - 1) : 0.f;
        float rmA = right_load ? __ldg(rowA + base + 8) : 0.f;
        float lmB = left_load  ? __ldg(rowB + base - 1) : 0.f;
        float rmB = right_load ? __ldg(rowB + base + 8) : 0.f;

        // Row A
        {
            float up = __shfl_up_sync(0xffffffffu, cva.w, 1);
            float dn = __shfl_down_sync(0xffffffffu, bva.x, 1);
            float vm1 = left_clamp  ? bva.x : (left_shfl  ? up : lmA);
            float vp8 = right_clamp ? cva.w : (right_shfl ? dn : rmA);
            float h0 = w0 * vm1    + w1 * bva.x + w2 * bva.y + w3 * bva.z;
            float h1 = w0 * bva.y  + w1 * bva.z + w2 * bva.w + w3 * cva.x;
            float h2 = w0 * bva.w  + w1 * cva.x + w2 * cva.y + w3 * cva.z;
            float h3 = w0 * cva.y  + w1 * cva.z + w2 * cva.w + w3 * vp8;
            float wi = wv[2 * pp];
            d0 = fmaf(wi, h0, d0);
            d1 = fmaf(wi, h1, d1);
            d2 = fmaf(wi, h2, d2);
            d3 = fmaf(wi, h3, d3);
        }
        // Row B
        {
            float up = __shfl_up_sync(0xffffffffu, cvb.w, 1);
            float dn = __shfl_down_sync(0xffffffffu, bvb.x, 1);
            float vm1 = left_clamp  ? bvb.x : (left_shfl  ? up : lmB);
            float vp8 = right_clamp ? cvb.w : (right_shfl ? dn : rmB);
            float h0 = w0 * vm1    + w1 * bvb.x + w2 * bvb.y + w3 * bvb.z;
            float h1 = w0 * bvb.y  + w1 * bvb.z + w2 * bvb.w + w3 * cvb.x;
            float h2 = w0 * bvb.w  + w1 * cvb.x + w2 * cvb.y + w3 * cvb.z;
            float h3 = w0 * cvb.y  + w1 * cvb.z + w2 * cvb.w + w3 * vp8;
            float wi = wv[2 * pp + 1];
            d0 = fmaf(wi, h0, d0);
            d1 = fmaf(wi, h1, d1);
            d2 = fmaf(wi, h2, d2);
            d3 = fmaf(wi, h3, d3);
        }
    }

    __syncthreads();   // order warp-0's sc[] writes before the reads below

    size_t p = (size_t)y * WOUT + (size_t)x4 * 4;   // float4-aligned pixel offset

    #pragma unroll
    for (int g = 0; g < 4; g++) {
        size_t chan = (size_t)(b * 64 + g * 16 + c);
        {
            float s = sc[g];
            __stcs(reinterpret_cast<float4*>(out + chan * PLANE + p),
                   make_float4(d0 * s, d1 * s, d2 * s, d3 * s));
        }
        #pragma unroll
        for (int band = 0; band < 3; band++) {
            float s = sc[4 + band * 4 + g];
            __stcs(reinterpret_cast<float4*>(out + LL_TOTAL + (chan * 3 + band) * PLANE + p),
                   make_float4(d0 * s, d1 * s, d2 * s, d3 * s));
        }
    }
}

extern "C" void kernel_launch(void* const* d_in, const int* in_sizes, int n_in,
                              void* d_out, int out_size) {
    const float* image = (const float*)d_in[0];
    const float* gl    = (const float*)d_in[1];
    const float* gh    = (const float*)d_in[2];
    const float* fl    = (const float*)d_in[3];
    const float* fh    = (const float*)d_in[4];
    float* out = (float*)d_out;

    // total threads = B*C*HOUT*(WOUT/4) = 4*16*256*64 = 1,048,576
    const int threads = 256;
    const int blocks = (B_ * C_ * HOUT * (WOUT / 4)) / threads;  // 4096
    qwt_kernel<<<blocks, threads>>>(image, gl, gh, fl, fh, out);
}

// round 14
// speedup vs baseline: 1.2657x; 1.2657x over previous
#include <cuda_runtime.h>

// ---------------------------------------------------------------------------
// QWTForward: bicubic 2x downsample + 16 scaled copies.
//
//   D = downsample_bicubic(image)                 (4,16,256,256)
//   LL[b, g*16+c]        = D[b,c] * sLL[g]        (4,64,256,256)
//   H [b, g*16+c, band]  = D[b,c] * sH[band][g]   (4,64,3,256,256)
//
// R10: barrier-free. Each warp: issue all 8 image loads first, compute the 4
// filter sums (serial index order — they cancel to ~1e-8, order is semantic)
// under the load shadow, shfl-broadcast, scales formed inline at store time.
// ---------------------------------------------------------------------------

#define B_    4
#define C_    16
#define HIN   512
#define WIN   512
#define HOUT  256
#define WOUT  256
#define PLANE (HOUT * WOUT)                // 65536
#define LL_TOTAL ((size_t)B_ * 64 * PLANE) // 16,777,216 floats

__global__ __launch_bounds__(256)
void qwt_kernel(const float* __restrict__ image,
                const float* __restrict__ gl,
                const float* __restrict__ gh,
                const float* __restrict__ fl,
                const float* __restrict__ fh,
                float* __restrict__ out) {
    const int lane = threadIdx.x & 31;

    // Linear thread id -> (b, c, y, x4); x4 selects 4 consecutive output x.
    unsigned gtid = blockIdx.x * blockDim.x + threadIdx.x;
    int x4 = gtid & 63;          // 64 float4 per row; consecutive within warp
    int y  = (gtid >> 6) & 255;
    int c  = (gtid >> 14) & 15;
    int b  = gtid >> 18;

    const float w0 = -0.09375f, w1 = 0.59375f, w2 = 0.59375f, w3 = -0.09375f;
    const float wv[4] = {w0, w1, w2, w3};

    const float* __restrict__ plane = image + (size_t)(b * C_ + c) * (HIN * WIN);

    int ry[4];
    #pragma unroll
    for (int i = 0; i < 4; i++) {
        int r = 2 * y - 1 + i;
        ry[i] = min(max(r, 0), HIN - 1);
    }

    const int base = 8 * x4;
    const bool left_clamp  = (x4 == 0);
    const bool left_shfl   = (!left_clamp) && (lane > 0);
    const bool right_clamp = (x4 == 63);
    const bool right_shfl  = (!right_clamp) && (lane < 31);
    const bool left_load   = (!left_clamp) && (lane == 0);
    const bool right_load  = (!right_clamp) && (lane == 31);

    // ---- Issue ALL image loads first (8 independent LDG.128 + edge halos) ----
    float4 bv[4], cv[4];
    #pragma unroll
    for (int i = 0; i < 4; i++) {
        const float4* __restrict__ row4 =
            reinterpret_cast<const float4*>(plane + (size_t)ry[i] * WIN);
        bv[i] = __ldg(row4 + 2 * x4);       // cols base .. base+3
        cv[i] = __ldg(row4 + 2 * x4 + 1);   // cols base+4 .. base+7
    }
    float lm[4], rm[4];
    #pragma unroll
    for (int i = 0; i < 4; i++) {
        const float* __restrict__ row = plane + (size_t)ry[i] * WIN;
        lm[i] = left_load  ? __ldg(row + base - 1) : 0.f;
        rm[i] = right_load ? __ldg(row + base + 8) : 0.f;
    }

    // ---- Filter sums under the load shadow (lanes 0-3, serial index order) ----
    float fs = 0.f;
    if (lane < 4) {
        const float* __restrict__ f =
            (lane == 0) ? gl : (lane == 1) ? gh : (lane == 2) ? fl : fh;
        #pragma unroll
        for (int i = 0; i < 16; i++) fs += f[i];
    }
    const float vg = __shfl_sync(0xffffffffu, fs, 0);  // sum(gl)
    const float vh = __shfl_sync(0xffffffffu, fs, 1);  // sum(gh)
    const float vl = __shfl_sync(0xffffffffu, fs, 2);  // sum(fl)
    const float vf = __shfl_sync(0xffffffffu, fs, 3);  // sum(fh)

    // ---- Shuffle halos + horizontal/vertical convolution ----
    float d0 = 0.f, d1 = 0.f, d2 = 0.f, d3 = 0.f;
    #pragma unroll
    for (int i = 0; i < 4; i++) {
        float up = __shfl_up_sync(0xffffffffu, cv[i].w, 1);
        float dn = __shfl_down_sync(0xffffffffu, bv[i].x, 1);
        float vm1 = left_clamp  ? bv[i].x : (left_shfl  ? up : lm[i]);
        float vp8 = right_clamp ? cv[i].w : (right_shfl ? dn : rm[i]);

        float h0 = w0 * vm1      + w1 * bv[i].x + w2 * bv[i].y + w3 * bv[i].z;
        float h1 = w0 * bv[i].y  + w1 * bv[i].z + w2 * bv[i].w + w3 * cv[i].x;
        float h2 = w0 * bv[i].w  + w1 * cv[i].x + w2 * cv[i].y + w3 * cv[i].z;
        float h3 = w0 * cv[i].y  + w1 * cv[i].z + w2 * cv[i].w + w3 * vp8;

        float wi = wv[i];
        d0 = fmaf(wi, h0, d0);
        d1 = fmaf(wi, h1, d1);
        d2 = fmaf(wi, h2, d2);
        d3 = fmaf(wi, h3, d3);
    }

    size_t p = (size_t)y * WOUT + (size_t)x4 * 4;   // float4-aligned pixel offset

    // Scales inline: every sub-band scale is a product of two of {vg,vh,vl,vf};
    // g and band are unrolled constants so the selects are compile-time.
    #pragma unroll
    for (int g = 0; g < 4; g++) {
        size_t chan = (size_t)(b * 64 + g * 16 + c);
        const float pA = (g & 1)  ? vl : vg;   // lowpass family factor
        const float pB = (g >> 1) ? vl : vg;
        const float hA = (g & 1)  ? vf : vh;   // highpass family factor
        const float hB = (g >> 1) ? vf : vh;
        {
            float s = pA * pB;                                   // LL
            __stcs(reinterpret_cast<float4*>(out + chan * PLANE + p),
                   make_float4(d0 * s, d1 * s, d2 * s, d3 * s));
        }
        {
            float s = pA * hB;                                   // band 1
            __stcs(reinterpret_cast<float4*>(out + LL_TOTAL + (chan * 3 + 0) * PLANE + p),
                   make_float4(d0 * s, d1 * s, d2 * s, d3 * s));
        }
        {
            float s = hA * pB;                                   // band 2
            __stcs(reinterpret_cast<float4*>(out + LL_TOTAL + (chan * 3 + 1) * PLANE + p),
                   make_float4(d0 * s, d1 * s, d2 * s, d3 * s));
        }
        {
            float s = hA * hB;                                   // band 3
            __stcs(reinterpret_cast<float4*>(out + LL_TOTAL + (chan * 3 + 2) * PLANE + p),
                   make_float4(d0 * s, d1 * s, d2 * s, d3 * s));
        }
    }
}

extern "C" void kernel_launch(void* const* d_in, const int* in_sizes, int n_in,
                              void* d_out, int out_size) {
    const float* image = (const float*)d_in[0];
    const float* gl    = (const float*)d_in[1];
    const float* gh    = (const float*)d_in[2];
    const float* fl    = (const float*)d_in[3];
    const float* fh    = (const float*)d_in[4];
    float* out = (float*)d_out;

    // total threads = B*C*HOUT*(WOUT/4) = 4*16*256*64 = 1,048,576
    const int threads = 256;
    const int blocks = (B_ * C_ * HOUT * (WOUT / 4)) / threads;  // 4096
    qwt_kernel<<<blocks, threads>>>(image, gl, gh, fl, fh, out);
}